// round 3
// baseline (speedup 1.0000x reference)
#include <cuda_runtime.h>
#include <cstdint>
#include <cstddef>

// ============================================================================
// Swarm6502: masked 5-expert MoE.
//   fu = fu_map[Op]; expert e processes tokens with fu==e.
//   h = gelu_tanh( concat_j emb_e[j, id_j] @ W1_e + b1_e )   (kD x 512)
//   out_seg = h @ B_e   (512 x nout_e), written to segment of 1296-wide row.
// Pipeline: zero -> compact -> pack(B2) -> gemm1(+gelu -> g_H) -> gemm2(scatter)
// Input order = setup_inputs() dict insertion order:
//   0-8 regs, 9 fu_map, 10-24 (emb,W1,b1)x5, 25-28 alu/logic Wr/Wf, 29-31 Wo.
// ============================================================================

#define NTOK 65536
#define HDIM 512
#define OUTW 1296

// ---------------- device scratch (static allocation only) -------------------
__device__ int   g_counts[5];
__device__ int   g_lists[5][NTOK];
__device__ float g_H[(size_t)NTOK * HDIM];        // 134 MB hidden scratch
__device__ float g_B2[2][512 * 264];              // packed [Wr|Wf] for alu/logic

// index source codes: 0=A 1=X 2=Y 3=SP 4=P 5=PCH 6=PCL 7=Op 8=Val 9=carry(P&1)
__constant__ int c_code[5][6] = {
    {0, 8, 9, 7, -1, -1},   // alu:   [A, Val, carry, Op]
    {0, 8, 9, 7, -1, -1},   // logic: [A, Val, carry, Op]
    {0, 1, 2, 8, 7, -1},    // move:  [A, X, Y, Val, Op]
    {5, 6, 4, 8, 3, 7},     // flow:  [PCH, PCL, P, Val, SP, Op]
    {0, 1, 3, 4, 8, 7}      // stack: [A, X, SP, P, Val, Op]
};
__constant__ int c_k[5]    = {4, 4, 5, 6, 6};
__constant__ int c_nout[5] = {264, 264, 256, 256, 256};
__constant__ int c_seg[5]  = {0, 264, 528, 784, 1040};

struct G1P {
    const int*   base[9];   // A X Y SP P PCH PCL Op Val
    const float* emb[5];
    const float* W1[5];
    const float* b1[5];
};
struct G2P {
    const float* B[5];      // Wo for e>=2; e<2 uses g_B2
    float*       out;
};

__device__ __forceinline__ float gelu_tanh(float x) {
    float x3 = x * x * x;
    float t  = tanhf(0.7978845608028654f * (x + 0.044715f * x3));
    return 0.5f * x * (1.0f + t);
}

// ---------------- kernel 0: zero output + counters ---------------------------
__global__ void zero_kernel(float4* __restrict__ out, long n4) {
    if (blockIdx.x == 0 && threadIdx.x < 5) g_counts[threadIdx.x] = 0;
    long i      = (long)blockIdx.x * blockDim.x + threadIdx.x;
    long stride = (long)gridDim.x * blockDim.x;
    float4 z = make_float4(0.f, 0.f, 0.f, 0.f);
    for (; i < n4; i += stride) out[i] = z;
}

// ---------------- kernel 1: per-expert token compaction ----------------------
__global__ void compact_kernel(const int* __restrict__ Op,
                               const int* __restrict__ fu_map) {
    int n = blockIdx.x * blockDim.x + threadIdx.x;
    if (n < NTOK) {
        int e   = fu_map[Op[n]];
        int pos = atomicAdd(&g_counts[e], 1);
        g_lists[e][pos] = n;
    }
}

// ---------------- kernel 2: pack [Wr | Wf] -> g_B2 (512 x 264) ---------------
__global__ void pack_b2(const float* __restrict__ aWr, const float* __restrict__ aWf,
                        const float* __restrict__ lWr, const float* __restrict__ lWf) {
    int total = 2 * 512 * 264;
    for (int i = blockIdx.x * blockDim.x + threadIdx.x; i < total;
         i += gridDim.x * blockDim.x) {
        int e   = i / (512 * 264);
        int rem = i - e * (512 * 264);
        int r   = rem / 264;
        int c   = rem - r * 264;
        const float* Wr = e ? lWr : aWr;
        const float* Wf = e ? lWf : aWf;
        g_B2[e][rem] = (c < 256) ? Wr[r * 256 + c] : Wf[r * 8 + (c - 256)];
    }
}

// ---------------- kernel 3: GEMM1 + gelu  (C x kD) @ (kD x 512) --------------
// tile: BM=128 tokens, BN=128 H-cols, BK=64 (one embedding chunk), 256 thr, 8x8
#define G1_SMEM (128 * 66 * 4 + 64 * 128 * 4)
__global__ void __launch_bounds__(256) gemm1_kernel(G1P p) {
    int e  = blockIdx.z;
    int C  = g_counts[e];
    int m0 = blockIdx.x * 128;
    if (m0 >= C) return;
    int n0 = blockIdx.y * 128;

    extern __shared__ float sm1[];
    float (*As)[66]  = (float(*)[66])sm1;                 // [m][k]
    float (*Bs)[128] = (float(*)[128])(sm1 + 128 * 66);   // [k][n]
    __shared__ int s_tok[128];
    __shared__ int s_idx[128];

    int tid = threadIdx.x;
    if (tid < 128) {
        int m = m0 + tid;
        s_tok[tid] = (m < C) ? g_lists[e][m] : -1;
    }
    __syncthreads();

    float acc[8][8];
#pragma unroll
    for (int i = 0; i < 8; i++)
#pragma unroll
        for (int j = 0; j < 8; j++) acc[i][j] = 0.f;

    int kc = c_k[e];
    const float* __restrict__ emb = p.emb[e];
    const float* __restrict__ W1  = p.W1[e];

    int rl = tid >> 4, c4 = tid & 15;     // A loads: 16 thr/row
    int rb = tid >> 5, cb = tid & 31;     // B loads: 32 thr/row
    int tm = (tid >> 4) * 8, tn = (tid & 15) * 8;

    for (int j = 0; j < kc; j++) {
        if (tid < 128) {
            int tok = s_tok[tid];
            int idx = 0;
            if (tok >= 0) {
                int code = c_code[e][j];
                idx = (code == 9) ? (p.base[4][tok] & 1) : p.base[code][tok];
            }
            s_idx[tid] = idx;
        }
        __syncthreads();
        // gather A tile: 128 rows x 64 cols from emb[j, idx, :]
#pragma unroll
        for (int pass = 0; pass < 8; pass++) {
            int m = pass * 16 + rl;
            float4 v = make_float4(0.f, 0.f, 0.f, 0.f);
            if (s_tok[m] >= 0) {
                const float4* rp =
                    (const float4*)(emb + ((size_t)j * 256 + s_idx[m]) * 64);
                v = __ldg(rp + c4);
            }
            float* d = &As[m][c4 * 4];
            *(float2*)d       = make_float2(v.x, v.y);
            *(float2*)(d + 2) = make_float2(v.z, v.w);
        }
        // load B tile: W1 rows j*64..+63, cols n0..n0+127
        const float* W1b = W1 + (size_t)j * 64 * HDIM + n0;
#pragma unroll
        for (int pass = 0; pass < 8; pass++) {
            int r = pass * 8 + rb;
            float4 v = __ldg((const float4*)(W1b + (size_t)r * HDIM) + cb);
            *(float4*)&Bs[r][cb * 4] = v;
        }
        __syncthreads();
#pragma unroll
        for (int k = 0; k < 64; k++) {
            float a[8], b[8];
#pragma unroll
            for (int i = 0; i < 8; i++) a[i] = As[tm + i][k];
            float4 b0  = *(const float4*)&Bs[k][tn];
            float4 b1v = *(const float4*)&Bs[k][tn + 4];
            b[0] = b0.x;  b[1] = b0.y;  b[2] = b0.z;  b[3] = b0.w;
            b[4] = b1v.x; b[5] = b1v.y; b[6] = b1v.z; b[7] = b1v.w;
#pragma unroll
            for (int i = 0; i < 8; i++)
#pragma unroll
                for (int jj = 0; jj < 8; jj++)
                    acc[i][jj] = fmaf(a[i], b[jj], acc[i][jj]);
        }
        __syncthreads();
    }

    // epilogue: bias + gelu -> g_H
    const float* b1p = p.b1[e] + n0 + tn;
    float bv[8];
#pragma unroll
    for (int jj = 0; jj < 8; jj++) bv[jj] = b1p[jj];
#pragma unroll
    for (int i = 0; i < 8; i++) {
        int tok = s_tok[tm + i];
        if (tok < 0) continue;
        float* h = g_H + (size_t)tok * HDIM + n0 + tn;
        float r[8];
#pragma unroll
        for (int jj = 0; jj < 8; jj++) r[jj] = gelu_tanh(acc[i][jj] + bv[jj]);
        *(float4*)h       = make_float4(r[0], r[1], r[2], r[3]);
        *(float4*)(h + 4) = make_float4(r[4], r[5], r[6], r[7]);
    }
}

// ---------------- kernel 4: GEMM2 + scatter  (C x 512) @ (512 x nout) --------
// tile: BM=128 tokens, BN=64 out-cols, BK=64, 256 thr, 8x4
#define G2_SMEM (128 * 66 * 4 + 64 * 64 * 4)
__global__ void __launch_bounds__(256) gemm2_kernel(G2P p) {
    int e    = blockIdx.z;
    int nout = c_nout[e];
    int n0   = blockIdx.y * 64;
    if (n0 >= nout) return;
    int C  = g_counts[e];
    int m0 = blockIdx.x * 128;
    if (m0 >= C) return;

    extern __shared__ float sm2[];
    float (*As)[66] = (float(*)[66])sm2;
    float (*Bs)[64] = (float(*)[64])(sm2 + 128 * 66);
    __shared__ int s_tok[128];

    int tid = threadIdx.x;
    if (tid < 128) {
        int m = m0 + tid;
        s_tok[tid] = (m < C) ? g_lists[e][m] : -1;
    }
    __syncthreads();

    float acc[8][4];
#pragma unroll
    for (int i = 0; i < 8; i++)
#pragma unroll
        for (int j = 0; j < 4; j++) acc[i][j] = 0.f;

    const float* __restrict__ B = (e < 2) ? g_B2[e] : p.B[e];
    int ldb   = nout;
    int ncols = nout - n0;   // 64 or 8 (tail tile of alu/logic)

    int rl = tid >> 4, c4 = tid & 15;
    int tm = (tid >> 4) * 8, tn = (tid & 15) * 4;

    for (int kk = 0; kk < HDIM; kk += 64) {
        // load A tile from g_H (rows gathered by token id)
#pragma unroll
        for (int pass = 0; pass < 8; pass++) {
            int m   = pass * 16 + rl;
            int tok = s_tok[m];
            float4 v = make_float4(0.f, 0.f, 0.f, 0.f);
            if (tok >= 0)
                v = __ldg((const float4*)(g_H + (size_t)tok * HDIM + kk) + c4);
            float* d = &As[m][c4 * 4];
            *(float2*)d       = make_float2(v.x, v.y);
            *(float2*)(d + 2) = make_float2(v.z, v.w);
        }
        // load B tile: rows kk..kk+63, cols n0..n0+63 (predicated on ncols)
#pragma unroll
        for (int pass = 0; pass < 4; pass++) {
            int r = pass * 16 + rl;
            float4 v = make_float4(0.f, 0.f, 0.f, 0.f);
            if (c4 * 4 < ncols)
                v = __ldg((const float4*)(B + (size_t)(kk + r) * ldb + n0) + c4);
            *(float4*)&Bs[r][c4 * 4] = v;
        }
        __syncthreads();
#pragma unroll
        for (int k = 0; k < 64; k++) {
            float a[8];
#pragma unroll
            for (int i = 0; i < 8; i++) a[i] = As[tm + i][k];
            float4 b4 = *(const float4*)&Bs[k][tn];
            float b[4] = {b4.x, b4.y, b4.z, b4.w};
#pragma unroll
            for (int i = 0; i < 8; i++)
#pragma unroll
                for (int jj = 0; jj < 4; jj++)
                    acc[i][jj] = fmaf(a[i], b[jj], acc[i][jj]);
        }
        __syncthreads();
    }

    if (tn < ncols) {
        int seg = c_seg[e];
#pragma unroll
        for (int i = 0; i < 8; i++) {
            int tok = s_tok[tm + i];
            if (tok < 0) continue;
            float4 v = make_float4(acc[i][0], acc[i][1], acc[i][2], acc[i][3]);
            *(float4*)(p.out + (size_t)tok * OUTW + seg + n0 + tn) = v;
        }
    }
}

// ---------------- host launcher ---------------------------------------------
extern "C" void kernel_launch(void* const* d_in, const int* in_sizes, int n_in,
                              void* d_out, int out_size) {
    (void)in_sizes; (void)n_in;
    // setup_inputs() dict-insertion order:
    // 0:A 1:X 2:Y 3:SP 4:P 5:PCH 6:PCL 7:Op 8:Val 9:fu_map
    // 10:alu_emb   11:alu_W1   12:alu_b1
    // 13:logic_emb 14:logic_W1 15:logic_b1
    // 16:move_emb  17:move_W1  18:move_b1
    // 19:flow_emb  20:flow_W1  21:flow_b1
    // 22:stack_emb 23:stack_W1 24:stack_b1
    // 25:alu_Wr 26:alu_Wf 27:logic_Wr 28:logic_Wf
    // 29:move_Wo 30:flow_Wo 31:stack_Wo
    cudaFuncSetAttribute(gemm1_kernel,
                         cudaFuncAttributeMaxDynamicSharedMemorySize, G1_SMEM);
    cudaFuncSetAttribute(gemm2_kernel,
                         cudaFuncAttributeMaxDynamicSharedMemorySize, G2_SMEM);

    G1P p1;
    for (int i = 0; i < 9; i++) p1.base[i] = (const int*)d_in[i];
    const int* Op = (const int*)d_in[7];
    const int* fu = (const int*)d_in[9];
    for (int e = 0; e < 5; e++) {
        p1.emb[e] = (const float*)d_in[10 + 3 * e];
        p1.W1[e]  = (const float*)d_in[11 + 3 * e];
        p1.b1[e]  = (const float*)d_in[12 + 3 * e];
    }
    G2P p2;
    p2.out  = (float*)d_out;
    p2.B[0] = nullptr;
    p2.B[1] = nullptr;
    p2.B[2] = (const float*)d_in[29];   // move_Wo
    p2.B[3] = (const float*)d_in[30];   // flow_Wo
    p2.B[4] = (const float*)d_in[31];   // stack_Wo

    long n4 = (long)out_size / 4;
    zero_kernel<<<2048, 256>>>((float4*)d_out, n4);
    compact_kernel<<<NTOK / 256, 256>>>(Op, fu);
    pack_b2<<<528, 512>>>((const float*)d_in[25], (const float*)d_in[26],
                          (const float*)d_in[27], (const float*)d_in[28]);
    gemm1_kernel<<<dim3(512, 4, 5), 256, G1_SMEM>>>(p1);
    gemm2_kernel<<<dim3(512, 5, 5), 256, G2_SMEM>>>(p2);
}

// round 5
// speedup vs baseline: 1.6682x; 1.6682x over previous
#include <cuda_runtime.h>
#include <cstdint>
#include <cstddef>

// ============================================================================
// Swarm6502 masked 5-expert MoE.
// R5 (= R4 resubmit; container infra failed): GEMM1 eliminated via per-slot
// lookup tables:
//   T[e][j] = emb_e[j] @ W1_e[j*64:(j+1)*64]    (256 x 512 per (e,j))
//   h[tok]  = gelu( sum_j T[e][j][id_j] + b1 )  (gather-sum, L2-bound)
// Pipeline: init -> compact -> precompute_T -> h_kernel -> flags -> gemm2
// gemm2 writes its 256 cols AND zero-fills the token-row complement (y==0).
// ============================================================================

#define NTOK 65536
#define HDIM 512
#define OUTW 1296

// ---------------- device scratch ---------------------------------------------
__device__ int   g_counts[5];
__device__ int   g_lists[5][NTOK];
__device__ float g_H[(size_t)NTOK * HDIM];           // 134 MB hidden
__device__ float g_T[(size_t)5 * 6 * 256 * HDIM];    // 31.5 MB lookup tables

// index source codes: 0=A 1=X 2=Y 3=SP 4=P 5=PCH 6=PCL 7=Op 8=Val 9=carry(P&1)
__constant__ int c_code[5][6] = {
    {0, 8, 9, 7, -1, -1},   // alu:   [A, Val, carry, Op]
    {0, 8, 9, 7, -1, -1},   // logic: [A, Val, carry, Op]
    {0, 1, 2, 8, 7, -1},    // move:  [A, X, Y, Val, Op]
    {5, 6, 4, 8, 3, 7},     // flow:  [PCH, PCL, P, Val, SP, Op]
    {0, 1, 3, 4, 8, 7}      // stack: [A, X, SP, P, Val, Op]
};
__constant__ int c_k[5]    = {4, 4, 5, 6, 6};
__constant__ int c_nout[5] = {264, 264, 256, 256, 256};  // incl. flags
__constant__ int c_seg[5]  = {0, 264, 528, 784, 1040};

struct PTP { const float* emb[5]; const float* W1[5]; };
struct HP  { const int* base[9]; const float* b1[5]; };
struct FP  { const float* Wf[2]; float* out; };
struct G2P { const float* B[5]; float* out; };  // Wr(e<2) / Wo(e>=2), ld=256

__device__ __forceinline__ float gelu_tanh(float x) {
    float x3 = x * x * x;
    float t  = tanhf(0.7978845608028654f * (x + 0.044715f * x3));
    return 0.5f * x * (1.0f + t);
}

// ---------------- kernel: init counters ---------------------------------------
__global__ void init_counts() {
    if (threadIdx.x < 5) g_counts[threadIdx.x] = 0;
}

// ---------------- kernel: per-expert token compaction --------------------------
__global__ void compact_kernel(const int* __restrict__ Op,
                               const int* __restrict__ fu_map) {
    int n = blockIdx.x * blockDim.x + threadIdx.x;
    if (n < NTOK) {
        int e   = fu_map[Op[n]];
        int pos = atomicAdd(&g_counts[e], 1);
        g_lists[e][pos] = n;
    }
}

// ---------------- kernel: precompute T[e][j] = emb_ej @ W1_ej ------------------
// tile 64 vocab rows x 128 H-cols, K=64 one-shot; grid (4, 4, 30)
#define PT_SMEM ((64 * 65 + 64 * 128) * 4)
__global__ void __launch_bounds__(256) precompute_T(PTP p) {
    int z = blockIdx.z, e = z / 6, j = z % 6;
    if (j >= c_k[e]) return;
    int v0 = blockIdx.x * 64;
    int n0 = blockIdx.y * 128;

    extern __shared__ float smp[];
    float (*Es)[65]  = (float(*)[65])smp;                 // [v][d]
    float (*Ws)[128] = (float(*)[128])(smp + 64 * 65);    // [d][n]
    int tid = threadIdx.x;

    // load emb rows (64 x 64): 16 floats/thread
    {
        int r = tid >> 2, c = (tid & 3) * 16;
        const float* src = p.emb[e] + ((size_t)j * 256 + v0 + r) * 64 + c;
#pragma unroll
        for (int q = 0; q < 16; q++) Es[r][c + q] = __ldg(src + q);
    }
    // load W1 rows (64 x 128): 32 floats/thread
    {
        int r = tid >> 2, c0 = (tid & 3) * 32;
        const float4* src =
            (const float4*)(p.W1[e] + ((size_t)(j * 64 + r)) * HDIM + n0 + c0);
        float4* dst = (float4*)&Ws[r][c0];
#pragma unroll
        for (int q = 0; q < 8; q++) dst[q] = __ldg(src + q);
    }
    __syncthreads();

    float acc[4][8];
#pragma unroll
    for (int i = 0; i < 4; i++)
#pragma unroll
        for (int jj = 0; jj < 8; jj++) acc[i][jj] = 0.f;

    int tm = (tid >> 4) * 4, tn = (tid & 15) * 8;
#pragma unroll
    for (int k = 0; k < 64; k++) {
        float a[4], b[8];
#pragma unroll
        for (int i = 0; i < 4; i++) a[i] = Es[tm + i][k];
        float4 b0 = *(const float4*)&Ws[k][tn];
        float4 b1 = *(const float4*)&Ws[k][tn + 4];
        b[0] = b0.x; b[1] = b0.y; b[2] = b0.z; b[3] = b0.w;
        b[4] = b1.x; b[5] = b1.y; b[6] = b1.z; b[7] = b1.w;
#pragma unroll
        for (int i = 0; i < 4; i++)
#pragma unroll
            for (int jj = 0; jj < 8; jj++)
                acc[i][jj] = fmaf(a[i], b[jj], acc[i][jj]);
    }

    float* T = g_T + ((size_t)(e * 6 + j) * 256) * HDIM;
#pragma unroll
    for (int i = 0; i < 4; i++) {
        float* d = T + (size_t)(v0 + tm + i) * HDIM + n0 + tn;
        *(float4*)d       = make_float4(acc[i][0], acc[i][1], acc[i][2], acc[i][3]);
        *(float4*)(d + 4) = make_float4(acc[i][4], acc[i][5], acc[i][6], acc[i][7]);
    }
}

// ---------------- kernel: h = gelu(sum_j T[e][j][idx_j] + b1) ------------------
// 256 thr = 2 groups x 128; each group: one token at a time, thread t owns
// float4 column t. 64 tokens per block.
__global__ void __launch_bounds__(256) h_kernel(HP p) {
    int e  = blockIdx.y;
    int C  = g_counts[e];
    int m0 = blockIdx.x * 64;
    if (m0 >= C) return;

    int tid = threadIdx.x;
    int g   = tid >> 7, t = tid & 127;
    int kc  = c_k[e];
    float4 bias = __ldg((const float4*)p.b1[e] + t);

    int mEnd = m0 + 64;
    if (mEnd > C) mEnd = C;
    for (int mi = m0 + g; mi < mEnd; mi += 2) {
        int tok = g_lists[e][mi];
        float4 acc = bias;
        for (int j = 0; j < kc; j++) {
            int code = c_code[e][j];
            int idx  = (code == 9) ? (__ldg(p.base[4] + tok) & 1)
                                   : __ldg(p.base[code] + tok);
            const float4* row =
                (const float4*)(g_T + (((size_t)(e * 6 + j) * 256 + idx) << 9));
            float4 v = row[t];
            acc.x += v.x; acc.y += v.y; acc.z += v.z; acc.w += v.w;
        }
        float4 r;
        r.x = gelu_tanh(acc.x); r.y = gelu_tanh(acc.y);
        r.z = gelu_tanh(acc.z); r.w = gelu_tanh(acc.w);
        ((float4*)(g_H + ((size_t)tok << 9)))[t] = r;
    }
}

// ---------------- kernel: flag cols (alu/logic): out[:,256..263] = h @ Wf ------
// block: 32 tokens x 8 flags = 256 threads; Wf staged in smem.
__global__ void __launch_bounds__(256) flag_kernel(FP p) {
    int e  = blockIdx.y;             // 0 or 1
    int C  = g_counts[e];
    int m0 = blockIdx.x * 32;
    if (m0 >= C) return;

    __shared__ float sWf[HDIM][8];   // 16 KB
    int tid = threadIdx.x;
    const float4* Wf4 = (const float4*)p.Wf[e];
#pragma unroll
    for (int i = 0; i < 4; i++)
        ((float4*)sWf)[tid + i * 256] = __ldg(Wf4 + tid + i * 256);
    __syncthreads();

    int r = tid >> 3, f = tid & 7;
    int mi = m0 + r;
    if (mi >= C) return;
    int tok = g_lists[e][mi];
    const float4* h = (const float4*)(g_H + ((size_t)tok << 9));
    float dot = 0.f;
#pragma unroll 4
    for (int k4 = 0; k4 < 128; k4++) {
        float4 hv = __ldg(h + k4);
        dot += hv.x * sWf[k4 * 4 + 0][f];
        dot += hv.y * sWf[k4 * 4 + 1][f];
        dot += hv.z * sWf[k4 * 4 + 2][f];
        dot += hv.w * sWf[k4 * 4 + 3][f];
    }
    p.out[(size_t)tok * OUTW + c_seg[e] + 256 + f] = dot;
}

// ---------------- kernel: GEMM2 + scatter + zero-fill --------------------------
// (C x 512) @ (512 x 256): BM=128, BN=128, BK=64, 256 thr, 8x8.
// y==0 blocks also zero the complement of the token's 1296-wide row.
#define G2_SMEM (128 * 66 * 4 + 64 * 128 * 4)
__global__ void __launch_bounds__(256) gemm2_kernel(G2P p) {
    int e  = blockIdx.z;
    int C  = g_counts[e];
    int m0 = blockIdx.x * 128;
    if (m0 >= C) return;
    int n0 = blockIdx.y * 128;

    extern __shared__ float sm2[];
    float (*As)[66]  = (float(*)[66])sm2;
    float (*Bs)[128] = (float(*)[128])(sm2 + 128 * 66);
    __shared__ int s_tok[128];

    int tid = threadIdx.x;
    if (tid < 128) {
        int m = m0 + tid;
        s_tok[tid] = (m < C) ? g_lists[e][m] : -1;
    }
    __syncthreads();

    // zero-fill complement of output rows (fire-and-forget stores)
    if (blockIdx.y == 0) {
        int s4 = c_seg[e] >> 2;
        int e4 = (c_seg[e] + c_nout[e]) >> 2;
        float4* out4 = (float4*)p.out;
        float4 z = make_float4(0.f, 0.f, 0.f, 0.f);
        for (int u = tid; u < 128 * (OUTW / 4); u += 256) {
            int m = u / (OUTW / 4);
            int f = u - m * (OUTW / 4);
            if (f >= s4 && f < e4) continue;
            int tok = s_tok[m];
            if (tok < 0) continue;
            out4[(size_t)tok * (OUTW / 4) + f] = z;
        }
    }

    float acc[8][8];
#pragma unroll
    for (int i = 0; i < 8; i++)
#pragma unroll
        for (int j = 0; j < 8; j++) acc[i][j] = 0.f;

    const float* __restrict__ B = p.B[e];
    int rl = tid >> 4, c4 = tid & 15;     // A: 16 thr/row
    int rb = tid >> 5, cb = tid & 31;     // B: 32 thr/row
    int tm = (tid >> 4) * 8, tn = (tid & 15) * 8;

    for (int kk = 0; kk < HDIM; kk += 64) {
#pragma unroll
        for (int pass = 0; pass < 8; pass++) {
            int m   = pass * 16 + rl;
            int tok = s_tok[m];
            float4 v = make_float4(0.f, 0.f, 0.f, 0.f);
            if (tok >= 0)
                v = __ldg((const float4*)(g_H + (size_t)tok * HDIM + kk) + c4);
            float* d = &As[m][c4 * 4];
            *(float2*)d       = make_float2(v.x, v.y);
            *(float2*)(d + 2) = make_float2(v.z, v.w);
        }
        const float* Bb = B + (size_t)kk * 256 + n0;
#pragma unroll
        for (int pass = 0; pass < 8; pass++) {
            int r = pass * 8 + rb;
            float4 v = __ldg((const float4*)(Bb + (size_t)r * 256) + cb);
            *(float4*)&Bs[r][cb * 4] = v;
        }
        __syncthreads();
#pragma unroll
        for (int k = 0; k < 64; k++) {
            float a[8], b[8];
#pragma unroll
            for (int i = 0; i < 8; i++) a[i] = As[tm + i][k];
            float4 b0 = *(const float4*)&Bs[k][tn];
            float4 b1 = *(const float4*)&Bs[k][tn + 4];
            b[0] = b0.x; b[1] = b0.y; b[2] = b0.z; b[3] = b0.w;
            b[4] = b1.x; b[5] = b1.y; b[6] = b1.z; b[7] = b1.w;
#pragma unroll
            for (int i = 0; i < 8; i++)
#pragma unroll
                for (int jj = 0; jj < 8; jj++)
                    acc[i][jj] = fmaf(a[i], b[jj], acc[i][jj]);
        }
        __syncthreads();
    }

    int seg = c_seg[e];
#pragma unroll
    for (int i = 0; i < 8; i++) {
        int tok = s_tok[tm + i];
        if (tok < 0) continue;
        float* o = p.out + (size_t)tok * OUTW + seg + n0 + tn;
        *(float4*)o       = make_float4(acc[i][0], acc[i][1], acc[i][2], acc[i][3]);
        *(float4*)(o + 4) = make_float4(acc[i][4], acc[i][5], acc[i][6], acc[i][7]);
    }
}

// ---------------- host launcher ------------------------------------------------
extern "C" void kernel_launch(void* const* d_in, const int* in_sizes, int n_in,
                              void* d_out, int out_size) {
    (void)in_sizes; (void)n_in; (void)out_size;
    // input order (setup_inputs dict order):
    // 0:A 1:X 2:Y 3:SP 4:P 5:PCH 6:PCL 7:Op 8:Val 9:fu_map
    // 10..24: (emb, W1, b1) x {alu, logic, move, flow, stack}
    // 25:alu_Wr 26:alu_Wf 27:logic_Wr 28:logic_Wf 29:move_Wo 30:flow_Wo 31:stack_Wo
    cudaFuncSetAttribute(precompute_T,
                         cudaFuncAttributeMaxDynamicSharedMemorySize, PT_SMEM);
    cudaFuncSetAttribute(gemm2_kernel,
                         cudaFuncAttributeMaxDynamicSharedMemorySize, G2_SMEM);

    PTP pt;
    HP  hp;
    for (int i = 0; i < 9; i++) hp.base[i] = (const int*)d_in[i];
    for (int e = 0; e < 5; e++) {
        pt.emb[e] = (const float*)d_in[10 + 3 * e];
        pt.W1[e]  = (const float*)d_in[11 + 3 * e];
        hp.b1[e]  = (const float*)d_in[12 + 3 * e];
    }
    FP fp;
    fp.Wf[0] = (const float*)d_in[26];   // alu_Wf
    fp.Wf[1] = (const float*)d_in[28];   // logic_Wf
    fp.out   = (float*)d_out;

    G2P p2;
    p2.out  = (float*)d_out;
    p2.B[0] = (const float*)d_in[25];    // alu_Wr
    p2.B[1] = (const float*)d_in[27];    // logic_Wr
    p2.B[2] = (const float*)d_in[29];    // move_Wo
    p2.B[3] = (const float*)d_in[30];    // flow_Wo
    p2.B[4] = (const float*)d_in[31];    // stack_Wo

    const int* Op = (const int*)d_in[7];
    const int* fu = (const int*)d_in[9];

    init_counts<<<1, 32>>>();
    compact_kernel<<<NTOK / 256, 256>>>(Op, fu);
    precompute_T<<<dim3(4, 4, 30), 256, PT_SMEM>>>(pt);
    h_kernel<<<dim3(1024, 5), 256>>>(hp);
    flag_kernel<<<dim3(2048, 2), 256>>>(fp);
    gemm2_kernel<<<dim3(512, 2, 5), 256, G2_SMEM>>>(p2);
}

// round 6
// speedup vs baseline: 2.2636x; 1.3569x over previous
#include <cuda_runtime.h>
#include <cstdint>
#include <cstddef>

// ============================================================================
// Swarm6502 masked 5-expert MoE.
// R6: gemm2 -> tf32 tensor cores (mma.sync m16n8k8), h_kernel 2-token unroll.
//   T[e][j] = emb_e[j] @ W1_e[j*64:(j+1)*64]
//   h[tok]  = gelu( sum_j T[e][j][id_j] + b1 )
//   out_seg = h @ B_e  (tf32 MMA, fp32 accumulate)
// ============================================================================

#define NTOK 65536
#define HDIM 512
#define OUTW 1296

__device__ int   g_counts[5];
__device__ int   g_lists[5][NTOK];
__device__ float g_H[(size_t)NTOK * HDIM];           // 134 MB hidden
__device__ float g_T[(size_t)5 * 6 * 256 * HDIM];    // 31.5 MB lookup tables

// index source codes: 0=A 1=X 2=Y 3=SP 4=P 5=PCH 6=PCL 7=Op 8=Val 9=carry(P&1)
__constant__ int c_code[5][6] = {
    {0, 8, 9, 7, -1, -1},   // alu
    {0, 8, 9, 7, -1, -1},   // logic
    {0, 1, 2, 8, 7, -1},    // move
    {5, 6, 4, 8, 3, 7},     // flow
    {0, 1, 3, 4, 8, 7}      // stack
};
__constant__ int c_k[5]    = {4, 4, 5, 6, 6};
__constant__ int c_nout[5] = {264, 264, 256, 256, 256};
__constant__ int c_seg[5]  = {0, 264, 528, 784, 1040};

struct PTP { const float* emb[5]; const float* W1[5]; };
struct HP  { const int* base[9]; const float* b1[5]; };
struct FP  { const float* Wf[2]; float* out; };
struct G2P { const float* B[5]; float* out; };

__device__ __forceinline__ float gelu_tanh(float x) {
    float x3 = x * x * x;
    float t  = tanhf(0.7978845608028654f * (x + 0.044715f * x3));
    return 0.5f * x * (1.0f + t);
}
__device__ __forceinline__ uint32_t f2tf32(float x) {
    uint32_t r;
    asm("cvt.rna.tf32.f32 %0, %1;" : "=r"(r) : "f"(x));
    return r;
}
__device__ __forceinline__ void mma_tf32(float* c, const uint32_t* a,
                                         const uint32_t* b) {
    asm volatile(
        "mma.sync.aligned.m16n8k8.row.col.f32.tf32.tf32.f32 "
        "{%0,%1,%2,%3}, {%4,%5,%6,%7}, {%8,%9}, {%0,%1,%2,%3};"
        : "+f"(c[0]), "+f"(c[1]), "+f"(c[2]), "+f"(c[3])
        : "r"(a[0]), "r"(a[1]), "r"(a[2]), "r"(a[3]), "r"(b[0]), "r"(b[1]));
}

// ---------------- init + compact ------------------------------------------------
__global__ void init_counts() {
    if (threadIdx.x < 5) g_counts[threadIdx.x] = 0;
}
__global__ void compact_kernel(const int* __restrict__ Op,
                               const int* __restrict__ fu_map) {
    int n = blockIdx.x * blockDim.x + threadIdx.x;
    if (n < NTOK) {
        int e   = fu_map[Op[n]];
        int pos = atomicAdd(&g_counts[e], 1);
        g_lists[e][pos] = n;
    }
}

// ---------------- precompute T[e][j] = emb_ej @ W1_ej ---------------------------
#define PT_SMEM ((64 * 65 + 64 * 128) * 4)
__global__ void __launch_bounds__(256) precompute_T(PTP p) {
    int z = blockIdx.z, e = z / 6, j = z % 6;
    if (j >= c_k[e]) return;
    int v0 = blockIdx.x * 64;
    int n0 = blockIdx.y * 128;

    extern __shared__ float smp[];
    float (*Es)[65]  = (float(*)[65])smp;
    float (*Ws)[128] = (float(*)[128])(smp + 64 * 65);
    int tid = threadIdx.x;

    {
        int r = tid >> 2, c = (tid & 3) * 16;
        const float* src = p.emb[e] + ((size_t)j * 256 + v0 + r) * 64 + c;
#pragma unroll
        for (int q = 0; q < 16; q++) Es[r][c + q] = __ldg(src + q);
    }
    {
        int r = tid >> 2, c0 = (tid & 3) * 32;
        const float4* src =
            (const float4*)(p.W1[e] + ((size_t)(j * 64 + r)) * HDIM + n0 + c0);
        float4* dst = (float4*)&Ws[r][c0];
#pragma unroll
        for (int q = 0; q < 8; q++) dst[q] = __ldg(src + q);
    }
    __syncthreads();

    float acc[4][8];
#pragma unroll
    for (int i = 0; i < 4; i++)
#pragma unroll
        for (int jj = 0; jj < 8; jj++) acc[i][jj] = 0.f;

    int tm = (tid >> 4) * 4, tn = (tid & 15) * 8;
#pragma unroll
    for (int k = 0; k < 64; k++) {
        float a[4], b[8];
#pragma unroll
        for (int i = 0; i < 4; i++) a[i] = Es[tm + i][k];
        float4 b0 = *(const float4*)&Ws[k][tn];
        float4 b1 = *(const float4*)&Ws[k][tn + 4];
        b[0] = b0.x; b[1] = b0.y; b[2] = b0.z; b[3] = b0.w;
        b[4] = b1.x; b[5] = b1.y; b[6] = b1.z; b[7] = b1.w;
#pragma unroll
        for (int i = 0; i < 4; i++)
#pragma unroll
            for (int jj = 0; jj < 8; jj++)
                acc[i][jj] = fmaf(a[i], b[jj], acc[i][jj]);
    }

    float* T = g_T + ((size_t)(e * 6 + j) * 256) * HDIM;
#pragma unroll
    for (int i = 0; i < 4; i++) {
        float* d = T + (size_t)(v0 + tm + i) * HDIM + n0 + tn;
        *(float4*)d       = make_float4(acc[i][0], acc[i][1], acc[i][2], acc[i][3]);
        *(float4*)(d + 4) = make_float4(acc[i][4], acc[i][5], acc[i][6], acc[i][7]);
    }
}

// ---------------- h = gelu(sum_j T[e][j][idx_j] + b1), 2-token unroll ------------
__global__ void __launch_bounds__(256) h_kernel(HP p) {
    int e  = blockIdx.y;
    int C  = g_counts[e];
    int m0 = blockIdx.x * 64;
    if (m0 >= C) return;

    int tid = threadIdx.x;
    int g   = tid >> 7, t = tid & 127;
    int kc  = c_k[e];
    float4 bias = __ldg((const float4*)p.b1[e] + t);
    const float* Tb = g_T + ((size_t)(e * 6) << 17);   // e*6*256*512

    int mEnd = m0 + 64;
    if (mEnd > C) mEnd = C;
    int mi = m0 + g;
    for (; mi + 2 < mEnd; mi += 4) {
        int tok0 = g_lists[e][mi];
        int tok1 = g_lists[e][mi + 2];
        float4 acc0 = bias, acc1 = bias;
        for (int j = 0; j < kc; j++) {
            int code = c_code[e][j];
            int i0 = (code == 9) ? (__ldg(p.base[4] + tok0) & 1)
                                 : __ldg(p.base[code] + tok0);
            int i1 = (code == 9) ? (__ldg(p.base[4] + tok1) & 1)
                                 : __ldg(p.base[code] + tok1);
            const float4* r0 = (const float4*)(Tb + (((size_t)j * 256 + i0) << 9));
            const float4* r1 = (const float4*)(Tb + (((size_t)j * 256 + i1) << 9));
            float4 v0 = r0[t], v1 = r1[t];
            acc0.x += v0.x; acc0.y += v0.y; acc0.z += v0.z; acc0.w += v0.w;
            acc1.x += v1.x; acc1.y += v1.y; acc1.z += v1.z; acc1.w += v1.w;
        }
        float4 o0, o1;
        o0.x = gelu_tanh(acc0.x); o0.y = gelu_tanh(acc0.y);
        o0.z = gelu_tanh(acc0.z); o0.w = gelu_tanh(acc0.w);
        o1.x = gelu_tanh(acc1.x); o1.y = gelu_tanh(acc1.y);
        o1.z = gelu_tanh(acc1.z); o1.w = gelu_tanh(acc1.w);
        ((float4*)(g_H + ((size_t)tok0 << 9)))[t] = o0;
        ((float4*)(g_H + ((size_t)tok1 << 9)))[t] = o1;
    }
    for (; mi < mEnd; mi += 2) {
        int tok = g_lists[e][mi];
        float4 acc = bias;
        for (int j = 0; j < kc; j++) {
            int code = c_code[e][j];
            int idx  = (code == 9) ? (__ldg(p.base[4] + tok) & 1)
                                   : __ldg(p.base[code] + tok);
            const float4* row = (const float4*)(Tb + (((size_t)j * 256 + idx) << 9));
            float4 v = row[t];
            acc.x += v.x; acc.y += v.y; acc.z += v.z; acc.w += v.w;
        }
        float4 r;
        r.x = gelu_tanh(acc.x); r.y = gelu_tanh(acc.y);
        r.z = gelu_tanh(acc.z); r.w = gelu_tanh(acc.w);
        ((float4*)(g_H + ((size_t)tok << 9)))[t] = r;
    }
}

// ---------------- flag cols (alu/logic) -----------------------------------------
__global__ void __launch_bounds__(256) flag_kernel(FP p) {
    int e  = blockIdx.y;
    int C  = g_counts[e];
    int m0 = blockIdx.x * 32;
    if (m0 >= C) return;

    __shared__ float sWf[HDIM][8];
    int tid = threadIdx.x;
    const float4* Wf4 = (const float4*)p.Wf[e];
#pragma unroll
    for (int i = 0; i < 4; i++)
        ((float4*)sWf)[tid + i * 256] = __ldg(Wf4 + tid + i * 256);
    __syncthreads();

    int r = tid >> 3, f = tid & 7;
    int mi = m0 + r;
    if (mi >= C) return;
    int tok = g_lists[e][mi];
    const float4* h = (const float4*)(g_H + ((size_t)tok << 9));
    float dot = 0.f;
#pragma unroll 4
    for (int k4 = 0; k4 < 128; k4++) {
        float4 hv = __ldg(h + k4);
        dot += hv.x * sWf[k4 * 4 + 0][f];
        dot += hv.y * sWf[k4 * 4 + 1][f];
        dot += hv.z * sWf[k4 * 4 + 2][f];
        dot += hv.w * sWf[k4 * 4 + 3][f];
    }
    p.out[(size_t)tok * OUTW + c_seg[e] + 256 + f] = dot;
}

// ---------------- gemm2: tf32 tensor cores + scatter + zero-fill -----------------
// (C x 512) @ (512 x 256). BM=128, BN=128, BK=32. 8 warps; warp tile 32x64.
// A staged [k][m] tf32, B staged [k][n] tf32; mma.sync m16n8k8, fp32 accum.
__global__ void __launch_bounds__(256) gemm2_kernel(G2P p) {
    int e  = blockIdx.z;
    int C  = g_counts[e];
    int m0 = blockIdx.x * 128;
    if (m0 >= C) return;
    int n0 = blockIdx.y * 128;

    __shared__ uint32_t As[32][132];
    __shared__ uint32_t Bs[32][132];
    __shared__ int s_tok[128];

    int tid = threadIdx.x;
    if (tid < 128) {
        int m = m0 + tid;
        s_tok[tid] = (m < C) ? g_lists[e][m] : -1;
    }
    __syncthreads();

    // zero-fill complement of the 1296-wide rows (y==0 blocks only)
    if (blockIdx.y == 0) {
        int s4 = c_seg[e] >> 2;
        int e4 = (c_seg[e] + c_nout[e]) >> 2;
        float4* out4 = (float4*)p.out;
        float4 z = make_float4(0.f, 0.f, 0.f, 0.f);
        for (int u = tid; u < 128 * (OUTW / 4); u += 256) {
            int m = u / (OUTW / 4);
            int f = u - m * (OUTW / 4);
            if (f >= s4 && f < e4) continue;
            int tok = s_tok[m];
            if (tok < 0) continue;
            out4[(size_t)tok * (OUTW / 4) + f] = z;
        }
    }

    int lane = tid & 31, wrp = tid >> 5;
    int wm = (wrp & 3) * 32;        // warp row base (0,32,64,96)
    int wn = (wrp >> 2) * 64;       // warp col base (0,64)
    int grp = lane >> 2, th4 = lane & 3;

    float c[2][8][4];
#pragma unroll
    for (int mt = 0; mt < 2; mt++)
#pragma unroll
        for (int nt = 0; nt < 8; nt++)
#pragma unroll
            for (int i = 0; i < 4; i++) c[mt][nt][i] = 0.f;

    // staging assignments
    int sa_m  = tid & 127;            // token row
    int sa_kq = (tid >> 7) * 16;      // k sub-block (0 or 16)
    int sa_tok = s_tok[sa_m];
    const float4* arow =
        (sa_tok >= 0) ? (const float4*)(g_H + ((size_t)sa_tok << 9)) : (const float4*)g_H;
    int sb_k = tid >> 3;              // 0..31
    int sb_n = (tid & 7) * 16;        // 0..112

    const float* __restrict__ B = p.B[e];

    for (int kk = 0; kk < HDIM; kk += 32) {
        // stage A: 16 k-values of one token row -> As[k][m], tf32
        {
            const float4* src = arow + ((kk + sa_kq) >> 2);
            float4 v[4];
#pragma unroll
            for (int q = 0; q < 4; q++)
                v[q] = (sa_tok >= 0) ? __ldg(src + q)
                                     : make_float4(0.f, 0.f, 0.f, 0.f);
#pragma unroll
            for (int q = 0; q < 4; q++) {
                As[sa_kq + q * 4 + 0][sa_m] = f2tf32(v[q].x);
                As[sa_kq + q * 4 + 1][sa_m] = f2tf32(v[q].y);
                As[sa_kq + q * 4 + 2][sa_m] = f2tf32(v[q].z);
                As[sa_kq + q * 4 + 3][sa_m] = f2tf32(v[q].w);
            }
        }
        // stage B: Bs[k][n], tf32
        {
            const float4* src =
                (const float4*)(B + (size_t)(kk + sb_k) * 256 + n0 + sb_n);
#pragma unroll
            for (int q = 0; q < 4; q++) {
                float4 v = __ldg(src + q);
                uint4 u;
                u.x = f2tf32(v.x); u.y = f2tf32(v.y);
                u.z = f2tf32(v.z); u.w = f2tf32(v.w);
                *(uint4*)&Bs[sb_k][sb_n + q * 4] = u;
            }
        }
        __syncthreads();

#pragma unroll
        for (int k8 = 0; k8 < 32; k8 += 8) {
            uint32_t a[2][4], b[8][2];
#pragma unroll
            for (int mt = 0; mt < 2; mt++) {
                int mb = wm + mt * 16;
                a[mt][0] = As[k8 + th4][mb + grp];
                a[mt][1] = As[k8 + th4][mb + 8 + grp];
                a[mt][2] = As[k8 + th4 + 4][mb + grp];
                a[mt][3] = As[k8 + th4 + 4][mb + 8 + grp];
            }
#pragma unroll
            for (int nt = 0; nt < 8; nt++) {
                int nb = wn + nt * 8;
                b[nt][0] = Bs[k8 + th4][nb + grp];
                b[nt][1] = Bs[k8 + th4 + 4][nb + grp];
            }
#pragma unroll
            for (int mt = 0; mt < 2; mt++)
#pragma unroll
                for (int nt = 0; nt < 8; nt++)
                    mma_tf32(c[mt][nt], a[mt], b[nt]);
        }
        __syncthreads();
    }

    // epilogue: D rows = wm + mt*16 + grp (c0,c1) and +8 (c2,c3);
    // cols = n0 + wn + nt*8 + 2*th4 (+1)
    int seg = c_seg[e];
#pragma unroll
    for (int mt = 0; mt < 2; mt++) {
        int r0   = wm + mt * 16 + grp;
        int tok0 = s_tok[r0];
        int tok1 = s_tok[r0 + 8];
        if (tok0 >= 0) {
            float* o = p.out + (size_t)tok0 * OUTW + seg + n0 + wn + 2 * th4;
#pragma unroll
            for (int nt = 0; nt < 8; nt++)
                *(float2*)(o + nt * 8) = make_float2(c[mt][nt][0], c[mt][nt][1]);
        }
        if (tok1 >= 0) {
            float* o = p.out + (size_t)tok1 * OUTW + seg + n0 + wn + 2 * th4;
#pragma unroll
            for (int nt = 0; nt < 8; nt++)
                *(float2*)(o + nt * 8) = make_float2(c[mt][nt][2], c[mt][nt][3]);
        }
    }
}

// ---------------- host launcher ---------------------------------------------------
extern "C" void kernel_launch(void* const* d_in, const int* in_sizes, int n_in,
                              void* d_out, int out_size) {
    (void)in_sizes; (void)n_in; (void)out_size;
    // input order (setup_inputs dict order):
    // 0:A 1:X 2:Y 3:SP 4:P 5:PCH 6:PCL 7:Op 8:Val 9:fu_map
    // 10..24: (emb, W1, b1) x {alu, logic, move, flow, stack}
    // 25:alu_Wr 26:alu_Wf 27:logic_Wr 28:logic_Wf 29:move_Wo 30:flow_Wo 31:stack_Wo
    cudaFuncSetAttribute(precompute_T,
                         cudaFuncAttributeMaxDynamicSharedMemorySize, PT_SMEM);

    PTP pt;
    HP  hp;
    for (int i = 0; i < 9; i++) hp.base[i] = (const int*)d_in[i];
    for (int e = 0; e < 5; e++) {
        pt.emb[e] = (const float*)d_in[10 + 3 * e];
        pt.W1[e]  = (const float*)d_in[11 + 3 * e];
        hp.b1[e]  = (const float*)d_in[12 + 3 * e];
    }
    FP fp;
    fp.Wf[0] = (const float*)d_in[26];
    fp.Wf[1] = (const float*)d_in[28];
    fp.out   = (float*)d_out;

    G2P p2;
    p2.out  = (float*)d_out;
    p2.B[0] = (const float*)d_in[25];
    p2.B[1] = (const float*)d_in[27];
    p2.B[2] = (const float*)d_in[29];
    p2.B[3] = (const float*)d_in[30];
    p2.B[4] = (const float*)d_in[31];

    const int* Op = (const int*)d_in[7];
    const int* fu = (const int*)d_in[9];

    init_counts<<<1, 32>>>();
    compact_kernel<<<NTOK / 256, 256>>>(Op, fu);
    precompute_T<<<dim3(4, 4, 30), 256, PT_SMEM>>>(pt);
    h_kernel<<<dim3(1024, 5), 256>>>(hp);
    flag_kernel<<<dim3(2048, 2), 256>>>(fp);
    gemm2_kernel<<<dim3(512, 2, 5), 256>>>(p2);
}